// round 1
// baseline (speedup 1.0000x reference)
#include <cuda_runtime.h>

#define N_NODES 50000
#define M_NB    16
#define NCAPS   8
#define NHID    16
#define DIM     128
#define ROUTIT  6

// Scratch (no allocation allowed): ~76.8MB static device buffers.
__device__ float g_xn[N_NODES * DIM];  // normalized layer-0 input
__device__ float g_h1[N_NODES * DIM];  // layer-0 routing output (relu'd)
__device__ float g_y [N_NODES * DIM];  // relu(fc(h1)) normalized per capsule

// ---------------------------------------------------------------------------
// K1: per-capsule L2 normalize of raw x -> g_xn
// one thread per capsule (16 floats), float4 loads/stores
// ---------------------------------------------------------------------------
__global__ __launch_bounds__(256) void normalize_kernel(const float* __restrict__ x)
{
    int idx = blockIdx.x * blockDim.x + threadIdx.x;       // capsule index
    if (idx >= N_NODES * NCAPS) return;
    const float4* src = reinterpret_cast<const float4*>(x) + idx * 4;
    float4 v0 = src[0], v1 = src[1], v2 = src[2], v3 = src[3];
    float ss = v0.x*v0.x + v0.y*v0.y + v0.z*v0.z + v0.w*v0.w
             + v1.x*v1.x + v1.y*v1.y + v1.z*v1.z + v1.w*v1.w
             + v2.x*v2.x + v2.y*v2.y + v2.z*v2.z + v2.w*v2.w
             + v3.x*v3.x + v3.y*v3.y + v3.z*v3.z + v3.w*v3.w;
    // x / max(||x||, 1e-12) == x * rsqrt(max(ss, 1e-24))
    float inv = rsqrtf(fmaxf(ss, 1e-24f));
    float4* dst = reinterpret_cast<float4*>(g_xn) + idx * 4;
    v0.x*=inv; v0.y*=inv; v0.z*=inv; v0.w*=inv;
    v1.x*=inv; v1.y*=inv; v1.z*=inv; v1.w*=inv;
    v2.x*=inv; v2.y*=inv; v2.z*=inv; v2.w*=inv;
    v3.x*=inv; v3.y*=inv; v3.z*=inv; v3.w*=inv;
    dst[0]=v0; dst[1]=v1; dst[2]=v2; dst[3]=v3;
}

// ---------------------------------------------------------------------------
// Routing body: one node per 128-thread block.
//   src   : per-capsule-normalized features [N,128] (also the xn / u-init)
//   out   : relu(u_final) [N,128]
// ---------------------------------------------------------------------------
__device__ __forceinline__ void routing_body(const float* __restrict__ src,
                                             const int*   __restrict__ nb,
                                             float*       __restrict__ out)
{
    // z smem layout: zs[m*136 + k*17 + d]  (k-stride 17 => phase-A conflict-free)
    __shared__ __align__(16) float zs[M_NB * 136];
    __shared__ __align__(16) float us[NCAPS * 20];      // u[k*20+d], float4-loadable
    __shared__ __align__(16) float ps[NCAPS * 16];      // p[k*16+m], float4-loadable
    __shared__ int nbs[M_NB];

    const int t    = threadIdx.x;
    const int node = blockIdx.x;

    if (t < M_NB) nbs[t] = nb[node * M_NB + t];

    const int kB = t >> 4;          // phase-B capsule
    const int dB = t & 15;          // phase-B dim

    const float xn = src[node * DIM + t];
    float u = xn;
    us[kB * 20 + dB] = xn;
    __syncthreads();

    // Gather: z[m][kB][dB] into registers (phase-B layout) and smem (phase-A layout)
    float zr[M_NB];
#pragma unroll
    for (int m = 0; m < M_NB; m++) {
        float v = src[nbs[m] * DIM + t];    // coalesced 512B row read, L2-resident
        zr[m] = v;
        zs[m * 136 + kB * 17 + dB] = v;
    }
    __syncthreads();

    const int mA = t >> 3;          // phase-A neighbor
    const int kA = t & 7;           // phase-A capsule
    const float* zA = zs + mA * 136 + kA * 17;
    const float* uA = us + kA * 20;

#pragma unroll
    for (int it = 0; it < ROUTIT; it++) {
        // ---- phase A: s[mA][kA] = <z[mA][kA][:], u[kA][:]> ----
        float s = 0.f;
#pragma unroll
        for (int q = 0; q < 4; q++) {
            float4 uq = *reinterpret_cast<const float4*>(uA + 4 * q);
            s += zA[4*q + 0] * uq.x;
            s += zA[4*q + 1] * uq.y;
            s += zA[4*q + 2] * uq.z;
            s += zA[4*q + 3] * uq.w;
        }
        // softmax over kA: 8 consecutive lanes per mA
        float mx = s;
        mx = fmaxf(mx, __shfl_xor_sync(0xffffffffu, mx, 1));
        mx = fmaxf(mx, __shfl_xor_sync(0xffffffffu, mx, 2));
        mx = fmaxf(mx, __shfl_xor_sync(0xffffffffu, mx, 4));
        float e = __expf(s - mx);
        float sm = e;
        sm += __shfl_xor_sync(0xffffffffu, sm, 1);
        sm += __shfl_xor_sync(0xffffffffu, sm, 2);
        sm += __shfl_xor_sync(0xffffffffu, sm, 4);
        ps[kA * 16 + mA] = __fdividef(e, sm);
        __syncthreads();

        // ---- phase B: u[kB][dB] = xn + sum_m z[m][kB][dB] * p[m][kB] ----
        float acc = xn;
#pragma unroll
        for (int m4 = 0; m4 < 4; m4++) {
            float4 pq = *reinterpret_cast<const float4*>(ps + kB * 16 + 4 * m4);
            acc += zr[4*m4 + 0] * pq.x;
            acc += zr[4*m4 + 1] * pq.y;
            acc += zr[4*m4 + 2] * pq.z;
            acc += zr[4*m4 + 3] * pq.w;
        }
        u = acc;
        if (it < ROUTIT - 1) {
            // per-capsule renormalize over dB (16 consecutive lanes)
            float ss = u * u;
            ss += __shfl_xor_sync(0xffffffffu, ss, 1);
            ss += __shfl_xor_sync(0xffffffffu, ss, 2);
            ss += __shfl_xor_sync(0xffffffffu, ss, 4);
            ss += __shfl_xor_sync(0xffffffffu, ss, 8);
            u *= rsqrtf(fmaxf(ss, 1e-24f));
            us[kB * 20 + dB] = u;
        }
        __syncthreads();
    }

    out[node * DIM + t] = fmaxf(u, 0.f);
}

__global__ __launch_bounds__(128) void routing1_kernel(const int* __restrict__ nb)
{
    routing_body(g_xn, nb, g_h1);
}

__global__ __launch_bounds__(128) void routing2_kernel(const int* __restrict__ nb,
                                                       float* __restrict__ out)
{
    routing_body(g_y, nb, out);
}

// ---------------------------------------------------------------------------
// K3: y = normalize_per_capsule( relu( h1 @ W^T + b ) )  -> g_y
// Block: 32 nodes x 128 cols. 256 threads, each computes 4 nodes x 4 cols.
// ---------------------------------------------------------------------------
__global__ __launch_bounds__(256) void fc_kernel(const float* __restrict__ W,
                                                 const float* __restrict__ bias)
{
    __shared__ __align__(16) float Hs[32 * 36];     // Hs[node*36 + kk]
    __shared__ __align__(16) float Ws[32 * 132];    // Ws[kk*132 + j]  (transposed)

    const int t    = threadIdx.x;
    const int row0 = blockIdx.x * 32;
    const int ng   = t >> 5;        // warp id = node group (4 nodes)
    const int cg   = t & 31;        // col group (4 cols)
    const int c0   = cg * 4;

    float acc[4][4];
#pragma unroll
    for (int i = 0; i < 4; i++)
#pragma unroll
        for (int j = 0; j < 4; j++) acc[i][j] = 0.f;

    float bv[4];
#pragma unroll
    for (int j = 0; j < 4; j++) bv[j] = bias[c0 + j];

    const int lr = t >> 3;          // 0..31
    const int lc = t & 7;           // 0..7

    for (int kt = 0; kt < 4; kt++) {
        // H tile: 32 nodes x 32 k
        {
            int gr = row0 + lr;
            float4 hv = make_float4(0.f, 0.f, 0.f, 0.f);
            if (gr < N_NODES)
                hv = *reinterpret_cast<const float4*>(g_h1 + gr * DIM + kt * 32 + lc * 4);
            *reinterpret_cast<float4*>(Hs + lr * 36 + lc * 4) = hv;
        }
        // W tile transposed: Ws[kk][j]
#pragma unroll
        for (int r = 0; r < 4; r++) {
            int j = lr + 32 * r;
            float4 wv = *reinterpret_cast<const float4*>(W + j * DIM + kt * 32 + lc * 4);
            Ws[(lc * 4 + 0) * 132 + j] = wv.x;
            Ws[(lc * 4 + 1) * 132 + j] = wv.y;
            Ws[(lc * 4 + 2) * 132 + j] = wv.z;
            Ws[(lc * 4 + 3) * 132 + j] = wv.w;
        }
        __syncthreads();

#pragma unroll
        for (int kk = 0; kk < 32; kk++) {
            float4 wq = *reinterpret_cast<const float4*>(Ws + kk * 132 + c0);
            float h0 = Hs[(ng * 4 + 0) * 36 + kk];
            float h1v = Hs[(ng * 4 + 1) * 36 + kk];
            float h2 = Hs[(ng * 4 + 2) * 36 + kk];
            float h3 = Hs[(ng * 4 + 3) * 36 + kk];
            acc[0][0] += h0 * wq.x; acc[0][1] += h0 * wq.y; acc[0][2] += h0 * wq.z; acc[0][3] += h0 * wq.w;
            acc[1][0] += h1v * wq.x; acc[1][1] += h1v * wq.y; acc[1][2] += h1v * wq.z; acc[1][3] += h1v * wq.w;
            acc[2][0] += h2 * wq.x; acc[2][1] += h2 * wq.y; acc[2][2] += h2 * wq.z; acc[2][3] += h2 * wq.w;
            acc[3][0] += h3 * wq.x; acc[3][1] += h3 * wq.y; acc[3][2] += h3 * wq.z; acc[3][3] += h3 * wq.w;
        }
        __syncthreads();
    }

    // Epilogue: bias + relu, per-capsule normalize (4 lanes share a capsule), store
#pragma unroll
    for (int i = 0; i < 4; i++) {
        float v0 = fmaxf(acc[i][0] + bv[0], 0.f);
        float v1 = fmaxf(acc[i][1] + bv[1], 0.f);
        float v2 = fmaxf(acc[i][2] + bv[2], 0.f);
        float v3 = fmaxf(acc[i][3] + bv[3], 0.f);
        float ss = v0*v0 + v1*v1 + v2*v2 + v3*v3;
        ss += __shfl_xor_sync(0xffffffffu, ss, 1);
        ss += __shfl_xor_sync(0xffffffffu, ss, 2);
        float inv = rsqrtf(fmaxf(ss, 1e-24f));
        int gr = row0 + ng * 4 + i;
        if (gr < N_NODES) {
            *reinterpret_cast<float4*>(g_y + gr * DIM + c0) =
                make_float4(v0 * inv, v1 * inv, v2 * inv, v3 * inv);
        }
    }
}

// ---------------------------------------------------------------------------
extern "C" void kernel_launch(void* const* d_in, const int* in_sizes, int n_in,
                              void* d_out, int out_size)
{
    const float* x  = (const float*)d_in[0];
    const int*   nb = (const int*)  d_in[1];
    const float* w  = (const float*)d_in[2];
    const float* b  = (const float*)d_in[3];
    float* out = (float*)d_out;

    (void)in_sizes; (void)n_in; (void)out_size;

    int ncaps_total = N_NODES * NCAPS;
    normalize_kernel<<<(ncaps_total + 255) / 256, 256>>>(x);
    routing1_kernel<<<N_NODES, 128>>>(nb);
    fc_kernel<<<(N_NODES + 31) / 32, 256>>>(w, b);
    routing2_kernel<<<N_NODES, 128>>>(nb, out);
}

// round 3
// speedup vs baseline: 2.3726x; 2.3726x over previous
#include <cuda_runtime.h>

#define N_NODES 50000
#define M_NB    16
#define NCAPS   8
#define NHID    16
#define DIM     128
#define ROUTIT  6

#define FULLMASK 0xffffffffu

// Scratch (no allocation allowed): static device buffers.
__device__ float g_xn[N_NODES * DIM];  // normalized layer-0 input
__device__ float g_h1[N_NODES * DIM];  // layer-0 routing output (relu'd)
__device__ float g_y [N_NODES * DIM];  // normalize(relu(fc(h1)))

// ---------------------------------------------------------------------------
// K1: per-capsule L2 normalize of raw x -> g_xn
// ---------------------------------------------------------------------------
__global__ __launch_bounds__(256) void normalize_kernel(const float* __restrict__ x)
{
    int idx = blockIdx.x * blockDim.x + threadIdx.x;       // capsule index
    if (idx >= N_NODES * NCAPS) return;
    const float4* src = reinterpret_cast<const float4*>(x) + idx * 4;
    float4 v0 = src[0], v1 = src[1], v2 = src[2], v3 = src[3];
    float ss = v0.x*v0.x + v0.y*v0.y + v0.z*v0.z + v0.w*v0.w
             + v1.x*v1.x + v1.y*v1.y + v1.z*v1.z + v1.w*v1.w
             + v2.x*v2.x + v2.y*v2.y + v2.z*v2.z + v2.w*v2.w
             + v3.x*v3.x + v3.y*v3.y + v3.z*v3.z + v3.w*v3.w;
    float inv = rsqrtf(fmaxf(ss, 1e-24f));
    float4* dst = reinterpret_cast<float4*>(g_xn) + idx * 4;
    v0.x*=inv; v0.y*=inv; v0.z*=inv; v0.w*=inv;
    v1.x*=inv; v1.y*=inv; v1.z*=inv; v1.w*=inv;
    v2.x*=inv; v2.y*=inv; v2.z*=inv; v2.w*=inv;
    v3.x*=inv; v3.y*=inv; v3.z*=inv; v3.w*=inv;
    dst[0]=v0; dst[1]=v1; dst[2]=v2; dst[3]=v3;
}

// ---------------------------------------------------------------------------
// Warp-per-node routing. Lane L: capsule k = L>>2, dim-group dg = L&3
// (owns dims 4*dg..4*dg+3 of capsule k). All state in registers; no smem.
// ---------------------------------------------------------------------------
__device__ __forceinline__ void routing_warp(const float* __restrict__ src,
                                             const int*   __restrict__ nb,
                                             float*       __restrict__ out)
{
    const int lane = threadIdx.x & 31;
    const int node = blockIdx.x * 8 + (threadIdx.x >> 5);
    const int dg   = lane & 3;

    // Broadcast neighbor indices: lanes 0..15 load one each.
    int nbv = 0;
    if (lane < 16) nbv = nb[node * M_NB + lane];

    const float4* srcv = reinterpret_cast<const float4*>(src);

    // xn / u init: this lane's 4 floats.
    float4 xn = srcv[node * 32 + lane];
    float4 u  = xn;

    // Gather z: 16 neighbor rows, coalesced float4 per lane.
    float4 z[M_NB];
#pragma unroll
    for (int m = 0; m < M_NB; m++) {
        int row = __shfl_sync(FULLMASK, nbv, m);
        z[m] = srcv[row * 32 + lane];
    }

    const bool b1 = (dg >> 1) & 1;
    const bool b0 = dg & 1;
    const int  kbase = lane & ~3;       // first lane of this k-group

    float4 unew = xn;   // carries final (pre-relu) result out of the loop

#pragma unroll
    for (int it = 0; it < ROUTIT; it++) {
        // ---- phase A: a[m] = <z[m], u> partial over own 4 dims ----
        float a[M_NB];
#pragma unroll
        for (int m = 0; m < M_NB; m++) {
            a[m] = z[m].x * u.x + z[m].y * u.y + z[m].z * u.z + z[m].w * u.w;
        }

        // ---- reduce-scatter over the 4 dg-lanes (same k) ----
        // round 1: xor 2 resolves bit1 of m
        float b[8];
#pragma unroll
        for (int i = 0; i < 8; i++) {
            int lo = ((i >> 1) << 2) | (i & 1);   // m with bit1=0
            int hi = lo | 2;
            float keep = b1 ? a[hi] : a[lo];
            float send = b1 ? a[lo] : a[hi];
            b[i] = keep + __shfl_xor_sync(FULLMASK, send, 2);
        }
        // round 2: xor 1 resolves bit0 of m
        float s[4];
#pragma unroll
        for (int i = 0; i < 4; i++) {
            int lo = i << 1;
            int hi = lo | 1;
            float keep = b0 ? b[hi] : b[lo];
            float send = b0 ? b[lo] : b[hi];
            s[i] = keep + __shfl_xor_sync(FULLMASK, send, 1);
        }
        // Now s[i] = <z[m], u> for m = 4*i + dg (full dot).

        // ---- softmax over k (lanes stride 4). |s| <= 1 (unit vectors):
        //      no max-subtraction needed (softmax is shift-invariant). ----
        float e[4], t[4];
#pragma unroll
        for (int i = 0; i < 4; i++) { e[i] = __expf(s[i]); t[i] = e[i]; }
#pragma unroll
        for (int i = 0; i < 4; i++) t[i] += __shfl_xor_sync(FULLMASK, t[i], 4);
#pragma unroll
        for (int i = 0; i < 4; i++) t[i] += __shfl_xor_sync(FULLMASK, t[i], 8);
#pragma unroll
        for (int i = 0; i < 4; i++) t[i] += __shfl_xor_sync(FULLMASK, t[i], 16);
        float p[4];
#pragma unroll
        for (int i = 0; i < 4; i++) p[i] = __fdividef(e[i], t[i]);
        // p[i] = softmax weight for m = 4*i + dg, this k.

        // ---- phase B: unew = xn + sum_m p[m] * z[m] ----
        unew = xn;
#pragma unroll
        for (int i = 0; i < 4; i++) {
#pragma unroll
            for (int g = 0; g < 4; g++) {
                float pv = __shfl_sync(FULLMASK, p[i], kbase + g); // p[m=4i+g][k]
                float4 zm = z[4 * i + g];
                unew.x += pv * zm.x;
                unew.y += pv * zm.y;
                unew.z += pv * zm.z;
                unew.w += pv * zm.w;
            }
        }

        if (it < ROUTIT - 1) {
            // per-capsule renormalize: reduce ||unew||^2 over 4 dg-lanes
            float nsq = unew.x*unew.x + unew.y*unew.y + unew.z*unew.z + unew.w*unew.w;
            nsq += __shfl_xor_sync(FULLMASK, nsq, 1);
            nsq += __shfl_xor_sync(FULLMASK, nsq, 2);
            float inv = rsqrtf(fmaxf(nsq, 1e-24f));
            u.x = unew.x * inv; u.y = unew.y * inv;
            u.z = unew.z * inv; u.w = unew.w * inv;
        }
    }

    // relu + store
    float4 o;
    o.x = fmaxf(unew.x, 0.f); o.y = fmaxf(unew.y, 0.f);
    o.z = fmaxf(unew.z, 0.f); o.w = fmaxf(unew.w, 0.f);
    reinterpret_cast<float4*>(out)[node * 32 + lane] = o;
}

__global__ __launch_bounds__(256) void routing1_kernel(const int* __restrict__ nb)
{
    routing_warp(g_xn, nb, g_h1);
}

__global__ __launch_bounds__(256) void routing2_kernel(const int* __restrict__ nb,
                                                       float* __restrict__ out)
{
    routing_warp(g_y, nb, out);
}

// ---------------------------------------------------------------------------
// K3: y = normalize_per_capsule( relu( h1 @ W^T + b ) )  -> g_y
// Block: 32 nodes x 128 cols. 256 threads, each computes 4 nodes x 4 cols.
// ---------------------------------------------------------------------------
__global__ __launch_bounds__(256) void fc_kernel(const float* __restrict__ W,
                                                 const float* __restrict__ bias)
{
    __shared__ __align__(16) float Hs[32 * 36];     // Hs[node*36 + kk]
    __shared__ __align__(16) float Ws[32 * 132];    // Ws[kk*132 + j]  (transposed)

    const int t    = threadIdx.x;
    const int row0 = blockIdx.x * 32;
    const int ng   = t >> 5;        // warp id = node group (4 nodes)
    const int cg   = t & 31;        // col group (4 cols)
    const int c0   = cg * 4;

    float acc[4][4];
#pragma unroll
    for (int i = 0; i < 4; i++)
#pragma unroll
        for (int j = 0; j < 4; j++) acc[i][j] = 0.f;

    float bv[4];
#pragma unroll
    for (int j = 0; j < 4; j++) bv[j] = bias[c0 + j];

    const int lr = t >> 3;          // 0..31
    const int lc = t & 7;           // 0..7

    for (int kt = 0; kt < 4; kt++) {
        {
            int gr = row0 + lr;
            float4 hv = make_float4(0.f, 0.f, 0.f, 0.f);
            if (gr < N_NODES)
                hv = *reinterpret_cast<const float4*>(g_h1 + gr * DIM + kt * 32 + lc * 4);
            *reinterpret_cast<float4*>(Hs + lr * 36 + lc * 4) = hv;
        }
#pragma unroll
        for (int r = 0; r < 4; r++) {
            int j = lr + 32 * r;
            float4 wv = *reinterpret_cast<const float4*>(W + j * DIM + kt * 32 + lc * 4);
            Ws[(lc * 4 + 0) * 132 + j] = wv.x;
            Ws[(lc * 4 + 1) * 132 + j] = wv.y;
            Ws[(lc * 4 + 2) * 132 + j] = wv.z;
            Ws[(lc * 4 + 3) * 132 + j] = wv.w;
        }
        __syncthreads();

#pragma unroll
        for (int kk = 0; kk < 32; kk++) {
            float4 wq = *reinterpret_cast<const float4*>(Ws + kk * 132 + c0);
            float h0  = Hs[(ng * 4 + 0) * 36 + kk];
            float h1v = Hs[(ng * 4 + 1) * 36 + kk];
            float h2  = Hs[(ng * 4 + 2) * 36 + kk];
            float h3  = Hs[(ng * 4 + 3) * 36 + kk];
            acc[0][0] += h0 * wq.x; acc[0][1] += h0 * wq.y; acc[0][2] += h0 * wq.z; acc[0][3] += h0 * wq.w;
            acc[1][0] += h1v * wq.x; acc[1][1] += h1v * wq.y; acc[1][2] += h1v * wq.z; acc[1][3] += h1v * wq.w;
            acc[2][0] += h2 * wq.x; acc[2][1] += h2 * wq.y; acc[2][2] += h2 * wq.z; acc[2][3] += h2 * wq.w;
            acc[3][0] += h3 * wq.x; acc[3][1] += h3 * wq.y; acc[3][2] += h3 * wq.z; acc[3][3] += h3 * wq.w;
        }
        __syncthreads();
    }

#pragma unroll
    for (int i = 0; i < 4; i++) {
        float v0 = fmaxf(acc[i][0] + bv[0], 0.f);
        float v1 = fmaxf(acc[i][1] + bv[1], 0.f);
        float v2 = fmaxf(acc[i][2] + bv[2], 0.f);
        float v3 = fmaxf(acc[i][3] + bv[3], 0.f);
        float ss = v0*v0 + v1*v1 + v2*v2 + v3*v3;
        ss += __shfl_xor_sync(FULLMASK, ss, 1);
        ss += __shfl_xor_sync(FULLMASK, ss, 2);
        float inv = rsqrtf(fmaxf(ss, 1e-24f));
        int gr = row0 + ng * 4 + i;
        if (gr < N_NODES) {
            *reinterpret_cast<float4*>(g_y + gr * DIM + c0) =
                make_float4(v0 * inv, v1 * inv, v2 * inv, v3 * inv);
        }
    }
}

// ---------------------------------------------------------------------------
extern "C" void kernel_launch(void* const* d_in, const int* in_sizes, int n_in,
                              void* d_out, int out_size)
{
    const float* x  = (const float*)d_in[0];
    const int*   nb = (const int*)  d_in[1];
    const float* w  = (const float*)d_in[2];
    const float* b  = (const float*)d_in[3];
    float* out = (float*)d_out;

    (void)in_sizes; (void)n_in; (void)out_size;

    int ncaps_total = N_NODES * NCAPS;
    normalize_kernel<<<(ncaps_total + 255) / 256, 256>>>(x);
    routing1_kernel<<<N_NODES / 8, 256>>>(nb);        // 50000 = 6250 * 8
    fc_kernel<<<(N_NODES + 31) / 32, 256>>>(w, b);
    routing2_kernel<<<N_NODES / 8, 256>>>(nb, out);
}